// round 15
// baseline (speedup 1.0000x reference)
#include <cuda_runtime.h>
#include <cstdint>
#include <math.h>

#define PTS    8192
#define NB     4
#define NSETS  8                 // (batch, set): even = yhat, odd = y
#define NG     32                // 3D grid 32^3, cell 0.5
#define NCELL3 (NG * NG * NG)    // 32768
#define SLAB   (NG * NG)         // 1024 cells per z-slab
#define NSLAB  NG
#define GMIN   (-8.0f)
#define GINV   2.0f
#define PADP   64
#define NPAIR  (PADP + PTS / 2 + PADP)   // 4224 pairs
#define SMEM_PAIR_BYTES (NPAIR * 2 * 16) // 135168 B

__device__ float4 g_pp[NSETS][NPAIR * 2];     // {x0x1,y0y1},{z0z1,s0s1}
__device__ float4 g_q[NSETS][PTS];
__device__ int    g_hist[NSETS][NCELL3];      // zero at load; re-zeroed by scan1
__device__ int    g_start[NSETS][NCELL3];     // slab-local starts; post-scatter = ENDs
__device__ int    g_bsum[NSETS * NSLAB];      // per-slab totals
__device__ float  g_res[NSETS][PTS];
__device__ float  g_part[64];

__device__ __forceinline__ int snake_id(int bx, int by, int bz) {
    int iy = (bz & 1) ? (NG - 1 - by) : by;
    int ix = ((by + bz) & 1) ? (NG - 1 - bx) : bx;
    return (bz * NG + iy) * NG + ix;
}
__device__ __forceinline__ int cell_of(float x, float y, float z) {
    int bx = (int)fminf(fmaxf((x - GMIN) * GINV, 0.f), (float)(NG - 1));
    int by = (int)fminf(fmaxf((y - GMIN) * GINV, 0.f), (float)(NG - 1));
    int bz = (int)fminf(fmaxf((z - GMIN) * GINV, 0.f), (float)(NG - 1));
    return snake_id(bx, by, bz);
}

#define FMA_F32X2(d, a, b, c) \
    asm("fma.rn.f32x2 %0, %1, %2, %3;" : "=l"(d) : "l"(a), "l"(b), "l"(c))
#define UNPACK_F32X2(lo, hi, v) \
    asm("mov.b64 {%0, %1}, %2;" : "=f"(lo), "=f"(hi) : "l"(v))
__device__ __forceinline__ unsigned long long pack2f(float lo, float hi) {
    unsigned long long r;
    asm("mov.b64 %0, {%1, %2};" : "=l"(r) : "f"(lo), "f"(hi));
    return r;
}

// ---- launch 1: histogram ---------------------------------------------------
__global__ __launch_bounds__(512)
void hist_kernel(const float* __restrict__ yhat, const float* __restrict__ y)
{
    int gid = blockIdx.x * 512 + threadIdx.x;
    int g = gid >> 13, i = gid & 8191;
    const float* src = ((g & 1) ? y : yhat) + (size_t)(g >> 1) * PTS * 3;
    float x = src[3 * i], yy = src[3 * i + 1], z = src[3 * i + 2];
    atomicAdd(&g_hist[g][cell_of(x, yy, z)], 1);
}

// ---- launch 2: per-slab scan -> slab-local starts; totals; zero hist back --
__global__ __launch_bounds__(128)
void scan1_kernel()
{
    __shared__ int wsum[4];
    const int blk = blockIdx.x, s = blk >> 5, slab = blk & 31;
    const int t = threadIdx.x, lane = t & 31, warp = t >> 5;
    int4* h4 = (int4*)&g_hist[s][slab * SLAB];
    int4 a = h4[2 * t], b = h4[2 * t + 1];
    int4 z4 = make_int4(0, 0, 0, 0);
    h4[2 * t] = z4; h4[2 * t + 1] = z4;
    int tot = a.x + a.y + a.z + a.w + b.x + b.y + b.z + b.w;
    int inc = tot;
#pragma unroll
    for (int o = 1; o < 32; o <<= 1) {
        int u = __shfl_up_sync(0xffffffffu, inc, o);
        if (lane >= o) inc += u;
    }
    if (lane == 31) wsum[warp] = inc;
    __syncthreads();
    int woff = 0;
    for (int w = 0; w < 4; ++w) {
        int v = wsum[w];
        if (w < warp) woff += v;
    }
    int run = inc - tot + woff;
    int4 o1, o2;
    o1.x = run;       o1.y = run + a.x; o1.z = o1.y + a.y; o1.w = o1.z + a.z;
    run = o1.w + a.w;
    o2.x = run;       o2.y = run + b.x; o2.z = o2.y + b.y; o2.w = o2.z + b.z;
    run = o2.w + b.w;
    int4* s4 = (int4*)&g_start[s][slab * SLAB];
    s4[2 * t] = o1; s4[2 * t + 1] = o2;
    if (t == 127) g_bsum[s * NSLAB + slab] = run;
    if (slab == 0 && t < PADP) {
        g_pp[s][2 * t]     = make_float4(0.f, 0.f, 0.f, 0.f);
        g_pp[s][2 * t + 1] = make_float4(0.f, 0.f, 3.0e38f, 3.0e38f);
        int o = PADP + PTS / 2 + t;
        g_pp[s][2 * o]     = make_float4(0.f, 0.f, 0.f, 0.f);
        g_pp[s][2 * o + 1] = make_float4(0.f, 0.f, 3.0e38f, 3.0e38f);
    }
}

// ---- launch 3: scatter; post-scatter g_start[c] = slab-local END of c ------
__global__ __launch_bounds__(512)
void scatter_kernel(const float* __restrict__ yhat, const float* __restrict__ y)
{
    __shared__ int sb[NSLAB], off[NSLAB];
    const int bid = blockIdx.x;           // 128 blocks, 16 per set
    const int g = bid >> 4;
    const int t = threadIdx.x;
    if (t < NSLAB) sb[t] = g_bsum[g * NSLAB + t];
    __syncthreads();
    if (t < NSLAB) {
        int p = 0;
        for (int k = 0; k < t; ++k) p += sb[k];
        off[t] = p;
    }
    __syncthreads();

    const float* src = ((g & 1) ? y : yhat) + (size_t)(g >> 1) * PTS * 3;
    int i = (bid & 15) * 512 + t;
    float x = src[3 * i], yy = src[3 * i + 1], z = src[3 * i + 2];
    int cell = cell_of(x, yy, z);
    int pos = off[cell / SLAB] + atomicAdd(&g_start[g][cell], 1);
    float s = x * x + yy * yy + z * z;
    int pj = PADP + (pos >> 1), sl = pos & 1;
    float* pA = (float*)&g_pp[g][2 * pj];
    pA[sl] = x; pA[2 + sl] = yy; pA[4 + sl] = z; pA[6 + sl] = s;
    g_q[g][pos] = make_float4(x, yy, z, s);
}

// run begin of cell idx (slab-local, post-scatter semantics)
__device__ __forceinline__ int run_begin(const int* __restrict__ st, int idx) {
    return ((idx & (SLAB - 1)) == 0) ? 0 : __ldg(st + idx - 1);
}

// ---- launch 4 (ncu capture slot): search -----------------------------------
// SMEM-resident candidate set. Each LANE owns 2 adjacent queries (warp = 64
// consecutive snake queries -> window barely larger than 32-query case, so
// pairs/query nearly halves). Inner loop: 4 pairs batched (8 LDS.128 up
// front for MLP), both queries share each loaded pair.
// Exact: any point improving query q lies within r_q of q per axis, and the
// union box contains every lane's per-query box.
__global__ __launch_bounds__(256)
void search_kernel()
{
    extern __shared__ float4 spp4[];       // NPAIR*2
    __shared__ int off[NSLAB + 1];

    const int bid = blockIdx.x;            // 128 blocks; 16 per set
    const int qset = bid >> 4;
    const int pset = qset ^ 1;
    const int sub = bid & 15;
    const int t = threadIdx.x, warp = t >> 5, lane = t & 31;

    // cooperative copy of the candidate set into smem
    const float4* gp = &g_pp[pset][0];
    for (int i = t; i < NPAIR * 2; i += 256)
        spp4[i] = __ldg(gp + i);

    if (t < NSLAB) {
        int v = g_bsum[pset * NSLAB + t];
        int inc = v;
#pragma unroll
        for (int o = 1; o < 32; o <<= 1) {
            int u = __shfl_up_sync(0xffffffffu, inc, o);
            if (t >= o) inc += u;
        }
        off[t] = inc - v;
        if (t == 31) off[NSLAB] = inc;
    }
    __syncthreads();

    const ulonglong2* pp = (const ulonglong2*)spp4;
    const int* st = &g_start[pset][0];

    // interleaved warp-task: 8 warps x 16 subs = 128 tasks/set, 64 queries each
    const int qbase = (warp * 16 + sub) * 64;
    const int qi0 = qbase + 2 * lane, qi1 = qi0 + 1;
    float4 qa = __ldg(&g_q[qset][qi0]);
    float4 qb = __ldg(&g_q[qset][qi1]);

    unsigned long long q2x[2], q2y[2], q2z[2];
    q2x[0] = pack2f(-2.f * qa.x, -2.f * qa.x);
    q2y[0] = pack2f(-2.f * qa.y, -2.f * qa.y);
    q2z[0] = pack2f(-2.f * qa.z, -2.f * qa.z);
    q2x[1] = pack2f(-2.f * qb.x, -2.f * qb.x);
    q2y[1] = pack2f(-2.f * qb.y, -2.f * qb.y);
    q2z[1] = pack2f(-2.f * qb.z, -2.f * qb.z);

    float cx = __shfl_sync(0xffffffffu, qa.x, 16);
    float cy = __shfl_sync(0xffffffffu, qa.y, 16);
    float cz = __shfl_sync(0xffffffffu, qa.z, 16);
    int cellA = cell_of(cx, cy, cz);
    const int k0 = off[cellA / SLAB] + run_begin(st, cellA);
    const int k0p = PADP + (k0 >> 1);

    float bestA[2] = {3.0e38f, 3.0e38f};
    float bestB[2] = {3.0e38f, 3.0e38f};

#define PROC4(jj) do {                                                      \
        int _j = (jj);                                                      \
        ulonglong2 w[8];                                                    \
        _Pragma("unroll")                                                   \
        for (int p = 0; p < 4; ++p) {                                       \
            w[2 * p]     = pp[2 * (_j + p)];                                \
            w[2 * p + 1] = pp[2 * (_j + p) + 1];                            \
        }                                                                   \
        _Pragma("unroll")                                                   \
        for (int p = 0; p < 4; ++p) {                                       \
            _Pragma("unroll")                                               \
            for (int qq = 0; qq < 2; ++qq) {                                \
                unsigned long long d;                                       \
                FMA_F32X2(d, q2z[qq], w[2 * p + 1].x, w[2 * p + 1].y);      \
                FMA_F32X2(d, q2y[qq], w[2 * p].y, d);                       \
                FMA_F32X2(d, q2x[qq], w[2 * p].x, d);                       \
                float lo, hi;                                               \
                UNPACK_F32X2(lo, hi, d);                                    \
                bestA[qq] = fminf(bestA[qq], lo);                           \
                bestB[qq] = fminf(bestB[qq], hi);                           \
            }                                                               \
        }                                                                   \
    } while (0)

    // phase 1: fixed 32 pairs (64 snake-adjacent points) around anchor
#pragma unroll
    for (int c4 = 0; c4 < 8; ++c4) PROC4(k0p - 8 + 4 * c4);

    // per-query radii -> warp-union cell box
    float r0 = sqrtf(fmaxf(fminf(bestA[0], bestB[0]) + qa.w, 0.f));
    float r1 = sqrtf(fmaxf(fminf(bestA[1], bestB[1]) + qb.w, 0.f));
    float xmn = fminf(qa.x - r0, qb.x - r1), xmx = fmaxf(qa.x + r0, qb.x + r1);
    float ymn = fminf(qa.y - r0, qb.y - r1), ymx = fmaxf(qa.y + r0, qb.y + r1);
    float zmn = fminf(qa.z - r0, qb.z - r1), zmx = fmaxf(qa.z + r0, qb.z + r1);
#pragma unroll
    for (int o = 16; o > 0; o >>= 1) {
        xmn = fminf(xmn, __shfl_xor_sync(0xffffffffu, xmn, o));
        xmx = fmaxf(xmx, __shfl_xor_sync(0xffffffffu, xmx, o));
        ymn = fminf(ymn, __shfl_xor_sync(0xffffffffu, ymn, o));
        ymx = fmaxf(ymx, __shfl_xor_sync(0xffffffffu, ymx, o));
        zmn = fminf(zmn, __shfl_xor_sync(0xffffffffu, zmn, o));
        zmx = fmaxf(zmx, __shfl_xor_sync(0xffffffffu, zmx, o));
    }
    int bx0 = (int)fminf(fmaxf((xmn - GMIN) * GINV, 0.f), (float)(NG - 1));
    int bx1 = (int)fminf(fmaxf((xmx - GMIN) * GINV, 0.f), (float)(NG - 1));
    int by0 = (int)fminf(fmaxf((ymn - GMIN) * GINV, 0.f), (float)(NG - 1));
    int by1 = (int)fminf(fmaxf((ymx - GMIN) * GINV, 0.f), (float)(NG - 1));
    int bz0 = (int)fminf(fmaxf((zmn - GMIN) * GINV, 0.f), (float)(NG - 1));
    int bz1 = (int)fminf(fmaxf((zmx - GMIN) * GINV, 0.f), (float)(NG - 1));

    const int NYb = by1 - by0 + 1;
    const int NR  = NYb * (bz1 - bz0 + 1);

    // chunked row scan: 32 row bounds fetched lane-parallel, consumed by
    // shfl broadcast; pair loop overshoots to x4 (pads / rescans safe:
    // idempotent min, pad s = 3e38 never wins, >=64 trailing pad pairs)
    for (int cb = 0; cb < NR; cb += 32) {
        int ri = cb + lane;
        int2 bnd = make_int2(0, 0);
        if (ri < NR) {
            int by = by0 + ri % NYb;
            int bz = bz0 + ri / NYb;
            int iy  = (bz & 1) ? (NG - 1 - by) : by;
            int dir = (by + bz) & 1;
            int ic0 = dir ? (NG - 1 - bx1) : bx0;
            int ic1 = dir ? (NG - 1 - bx0) : bx1;
            int rowbase = (bz * NG + iy) * NG;
            int is = off[bz] + run_begin(st, rowbase + ic0);
            int ie = off[bz] + __ldg(st + rowbase + ic1);
            bnd = make_int2(PADP + (is >> 1), PADP + ((ie + 1) >> 1));
        }
        int nrows = min(32, NR - cb);
        for (int rr = 0; rr < nrows; ++rr) {
            int jb = __shfl_sync(0xffffffffu, bnd.x, rr);
            int je = __shfl_sync(0xffffffffu, bnd.y, rr);
            for (int j = jb; j < je; j += 4)
                PROC4(j);
        }
    }

    g_res[qset][qi0] = fmaxf(fminf(bestA[0], bestB[0]) + qa.w, 0.f);
    g_res[qset][qi1] = fmaxf(fminf(bestA[1], bestB[1]) + qb.w, 0.f);
}

// ---- launches 5+6: reduction ------------------------------------------------
__global__ void reduce_partial_kernel()
{
    const int t = threadIdx.x, bid = blockIdx.x;
    const float* r = (const float*)g_res;
    float s = 0.f;
#pragma unroll
    for (int k = 0; k < 4; ++k)
        s += r[bid * 1024 + k * 256 + t];
#pragma unroll
    for (int o = 16; o > 0; o >>= 1)
        s += __shfl_down_sync(0xffffffffu, s, o);
    __shared__ float sh[8];
    if ((t & 31) == 0) sh[t >> 5] = s;
    __syncthreads();
    if (t == 0) {
        float v = 0.f;
#pragma unroll
        for (int w = 0; w < 8; ++w) v += sh[w];
        g_part[bid] = v;
    }
}

__global__ void final_kernel(float* __restrict__ out)
{
    const int t = threadIdx.x;   // 32
    double s = (double)g_part[t] + (double)g_part[t + 32];
#pragma unroll
    for (int o = 16; o > 0; o >>= 1)
        s += __shfl_down_sync(0xffffffffu, s, o);
    if (t == 0)
        out[0] = (float)sqrt(0.5 * s / (double)(NB * PTS));
}

extern "C" void kernel_launch(void* const* d_in, const int* in_sizes, int n_in,
                              void* d_out, int out_size)
{
    const float* yhat = (const float*)d_in[0];   // [B, N, 3]
    const float* y    = (const float*)d_in[1];   // [B, M, 3]
    (void)in_sizes; (void)n_in; (void)out_size;

    cudaFuncSetAttribute(search_kernel,
                         cudaFuncAttributeMaxDynamicSharedMemorySize,
                         SMEM_PAIR_BYTES);

    hist_kernel<<<128, 512>>>(yhat, y);              // 1
    scan1_kernel<<<256, 128>>>();                    // 2
    scatter_kernel<<<128, 512>>>(yhat, y);           // 3
    search_kernel<<<128, 256, SMEM_PAIR_BYTES>>>();  // 4 <- ncu capture slot
    reduce_partial_kernel<<<64, 256>>>();            // 5
    final_kernel<<<1, 32>>>((float*)d_out);          // 6
}

// round 16
// speedup vs baseline: 1.8048x; 1.8048x over previous
#include <cuda_runtime.h>
#include <cstdint>
#include <math.h>

#define PTS    8192
#define NB     4
#define NSETS  8                 // (batch, set): even = yhat, odd = y
#define NG     32                // 3D grid 32^3, cell 0.5
#define NCELL3 (NG * NG * NG)    // 32768
#define SLAB   (NG * NG)         // 1024 cells per z-slab
#define NSLAB  NG
#define GMIN   (-8.0f)
#define GINV   2.0f
#define PADP   64
#define NPAIR  (PADP + PTS / 2 + PADP)   // 4224 pairs
#define SMEM_PAIRS  (NPAIR * 2 * 16)     // 135168 B
#define SMEM_TOTAL  (SMEM_PAIRS + NCELL3 * 2)  // +65536 = 200704 B

__device__ float4 g_pp[NSETS][NPAIR * 2];     // {x0x1,y0y1},{z0z1,s0s1}
__device__ float4 g_q[NSETS][PTS];
__device__ int    g_hist[NSETS][NCELL3];      // zero at load; re-zeroed by scan1
__device__ int    g_start[NSETS][NCELL3];     // slab-local starts; post-scatter = ENDs
__device__ int    g_bsum[NSETS * NSLAB];      // per-slab totals
__device__ float  g_res[NSETS][PTS];
__device__ float  g_part[64];

__device__ __forceinline__ int snake_id(int bx, int by, int bz) {
    int iy = (bz & 1) ? (NG - 1 - by) : by;
    int ix = ((by + bz) & 1) ? (NG - 1 - bx) : bx;
    return (bz * NG + iy) * NG + ix;
}
__device__ __forceinline__ int cell_of(float x, float y, float z) {
    int bx = (int)fminf(fmaxf((x - GMIN) * GINV, 0.f), (float)(NG - 1));
    int by = (int)fminf(fmaxf((y - GMIN) * GINV, 0.f), (float)(NG - 1));
    int bz = (int)fminf(fmaxf((z - GMIN) * GINV, 0.f), (float)(NG - 1));
    return snake_id(bx, by, bz);
}

#define FMA_F32X2(d, a, b, c) \
    asm("fma.rn.f32x2 %0, %1, %2, %3;" : "=l"(d) : "l"(a), "l"(b), "l"(c))
#define UNPACK_F32X2(lo, hi, v) \
    asm("mov.b64 {%0, %1}, %2;" : "=f"(lo), "=f"(hi) : "l"(v))
__device__ __forceinline__ unsigned long long pack2f(float lo, float hi) {
    unsigned long long r;
    asm("mov.b64 %0, {%1, %2};" : "=l"(r) : "f"(lo), "f"(hi));
    return r;
}

// ---- launch 1: histogram ---------------------------------------------------
__global__ __launch_bounds__(512)
void hist_kernel(const float* __restrict__ yhat, const float* __restrict__ y)
{
    int gid = blockIdx.x * 512 + threadIdx.x;
    int g = gid >> 13, i = gid & 8191;
    const float* src = ((g & 1) ? y : yhat) + (size_t)(g >> 1) * PTS * 3;
    float x = src[3 * i], yy = src[3 * i + 1], z = src[3 * i + 2];
    atomicAdd(&g_hist[g][cell_of(x, yy, z)], 1);
}

// ---- launch 2: per-slab scan -> slab-local starts; totals; zero hist back --
__global__ __launch_bounds__(128)
void scan1_kernel()
{
    __shared__ int wsum[4];
    const int blk = blockIdx.x, s = blk >> 5, slab = blk & 31;
    const int t = threadIdx.x, lane = t & 31, warp = t >> 5;
    int4* h4 = (int4*)&g_hist[s][slab * SLAB];
    int4 a = h4[2 * t], b = h4[2 * t + 1];
    int4 z4 = make_int4(0, 0, 0, 0);
    h4[2 * t] = z4; h4[2 * t + 1] = z4;
    int tot = a.x + a.y + a.z + a.w + b.x + b.y + b.z + b.w;
    int inc = tot;
#pragma unroll
    for (int o = 1; o < 32; o <<= 1) {
        int u = __shfl_up_sync(0xffffffffu, inc, o);
        if (lane >= o) inc += u;
    }
    if (lane == 31) wsum[warp] = inc;
    __syncthreads();
    int woff = 0;
    for (int w = 0; w < 4; ++w) {
        int v = wsum[w];
        if (w < warp) woff += v;
    }
    int run = inc - tot + woff;
    int4 o1, o2;
    o1.x = run;       o1.y = run + a.x; o1.z = o1.y + a.y; o1.w = o1.z + a.z;
    run = o1.w + a.w;
    o2.x = run;       o2.y = run + b.x; o2.z = o2.y + b.y; o2.w = o2.z + b.z;
    run = o2.w + b.w;
    int4* s4 = (int4*)&g_start[s][slab * SLAB];
    s4[2 * t] = o1; s4[2 * t + 1] = o2;
    if (t == 127) g_bsum[s * NSLAB + slab] = run;
    if (slab == 0 && t < PADP) {
        g_pp[s][2 * t]     = make_float4(0.f, 0.f, 0.f, 0.f);
        g_pp[s][2 * t + 1] = make_float4(0.f, 0.f, 3.0e38f, 3.0e38f);
        int o = PADP + PTS / 2 + t;
        g_pp[s][2 * o]     = make_float4(0.f, 0.f, 0.f, 0.f);
        g_pp[s][2 * o + 1] = make_float4(0.f, 0.f, 3.0e38f, 3.0e38f);
    }
}

// ---- launch 3: scatter; post-scatter g_start[c] = slab-local END of c ------
__global__ __launch_bounds__(512)
void scatter_kernel(const float* __restrict__ yhat, const float* __restrict__ y)
{
    __shared__ int sb[NSLAB], off[NSLAB];
    const int bid = blockIdx.x;           // 128 blocks, 16 per set
    const int g = bid >> 4;
    const int t = threadIdx.x;
    if (t < NSLAB) sb[t] = g_bsum[g * NSLAB + t];
    __syncthreads();
    if (t < NSLAB) {
        int p = 0;
        for (int k = 0; k < t; ++k) p += sb[k];
        off[t] = p;
    }
    __syncthreads();

    const float* src = ((g & 1) ? y : yhat) + (size_t)(g >> 1) * PTS * 3;
    int i = (bid & 15) * 512 + t;
    float x = src[3 * i], yy = src[3 * i + 1], z = src[3 * i + 2];
    int cell = cell_of(x, yy, z);
    int pos = off[cell / SLAB] + atomicAdd(&g_start[g][cell], 1);
    float s = x * x + yy * yy + z * z;
    int pj = PADP + (pos >> 1), sl = pos & 1;
    float* pA = (float*)&g_pp[g][2 * pj];
    pA[sl] = x; pA[2 + sl] = yy; pA[4 + sl] = z; pA[6 + sl] = s;
    g_q[g][pos] = make_float4(x, yy, z, s);
}

// ---- launch 4 (ncu capture slot): search -----------------------------------
// SMEM holds BOTH the pair array (135KB) and a u16 GLOBAL cell-ends table
// (64KB). Phase 1: broadcast 64 snake-adjacent points -> per-lane radius
// r >= d_NN. Phase 2: EACH LANE scans only its own cell box (own rows, own
// pairs) — one warp instruction = 32 useful pairs, warp time = max own-lane
// work, immune to union-box blowup. Exact: any point improving query q lies
// within r_q of q on every axis.
__global__ __launch_bounds__(512)
void search_kernel()
{
    extern __shared__ char smraw[];
    float4* spp4 = (float4*)smraw;                                   // NPAIR*2
    unsigned short* sends = (unsigned short*)(smraw + SMEM_PAIRS);   // NCELL3
    __shared__ int off[NSLAB];

    const int bid = blockIdx.x;            // 128 blocks; 16 per set
    const int qset = bid >> 4;
    const int pset = qset ^ 1;
    const int sub = bid & 15;
    const int t = threadIdx.x, warp = t >> 5, lane = t & 31;

    // slab offsets (exclusive scan of per-slab totals), warp 0
    if (t < NSLAB) {
        int v = g_bsum[pset * NSLAB + t];
        int inc = v;
#pragma unroll
        for (int o = 1; o < 32; o <<= 1) {
            int u = __shfl_up_sync(0xffffffffu, inc, o);
            if (t >= o) inc += u;
        }
        off[t] = inc - v;
    }
    __syncthreads();

    // cooperative copies: pairs + GLOBAL u16 ends table
    const float4* gp = &g_pp[pset][0];
    for (int i = t; i < NPAIR * 2; i += 512)
        spp4[i] = __ldg(gp + i);
    const int* st = &g_start[pset][0];
    for (int i = t; i < NCELL3; i += 512)
        sends[i] = (unsigned short)(off[i >> 10] + __ldg(st + i));
    __syncthreads();

    const ulonglong2* pp = (const ulonglong2*)spp4;

    // interleaved warp-task: 16 warps x 16 subs = 256 tasks/set? No:
    // 16 warps/block, 16 blocks/set -> task = warp*16+sub in [0,256) ... each
    // task takes 32 consecutive queries: 256*32 = 8192. Correct.
    const int qi = ((warp * 16 + sub) * 32) + lane;
    float4 q = __ldg(&g_q[qset][qi]);
    const float qx = q.x, qy = q.y, qz = q.z, sqq = q.w;
    const unsigned long long q2x = pack2f(-2.f * qx, -2.f * qx);
    const unsigned long long q2y = pack2f(-2.f * qy, -2.f * qy);
    const unsigned long long q2z = pack2f(-2.f * qz, -2.f * qz);

    float bestA = 3.0e38f, bestB = 3.0e38f;

#define PROCP(jj) do {                                                   \
        int _j = (jj);                                                   \
        ulonglong2 v0 = pp[2 * _j];                                      \
        ulonglong2 v1 = pp[2 * _j + 1];                                  \
        unsigned long long d;                                            \
        FMA_F32X2(d, q2z, v1.x, v1.y);                                   \
        FMA_F32X2(d, q2y, v0.y, d);                                      \
        FMA_F32X2(d, q2x, v0.x, d);                                      \
        float lo, hi;                                                    \
        UNPACK_F32X2(lo, hi, d);                                         \
        bestA = fminf(bestA, lo);                                        \
        bestB = fminf(bestB, hi);                                        \
    } while (0)

    // phase 1: 32 pairs (64 snake-adjacent points) around warp anchor
    {
        float cx = __shfl_sync(0xffffffffu, qx, 16);
        float cy = __shfl_sync(0xffffffffu, qy, 16);
        float cz = __shfl_sync(0xffffffffu, qz, 16);
        int cellA = cell_of(cx, cy, cz);
        int k0 = cellA ? sends[cellA - 1] : 0;          // global begin
        int k0p = PADP + (k0 >> 1);
#pragma unroll
        for (int jj = 0; jj < 32; ++jj) PROCP(k0p - 8 + jj);
    }

    // per-lane radius and OWN box
    float r = sqrtf(fmaxf(fminf(bestA, bestB) + sqq, 0.f));
    int bx0 = (int)fminf(fmaxf((qx - r - GMIN) * GINV, 0.f), (float)(NG - 1));
    int bx1 = (int)fminf(fmaxf((qx + r - GMIN) * GINV, 0.f), (float)(NG - 1));
    int by0 = (int)fminf(fmaxf((qy - r - GMIN) * GINV, 0.f), (float)(NG - 1));
    int by1 = (int)fminf(fmaxf((qy + r - GMIN) * GINV, 0.f), (float)(NG - 1));
    int bz0 = (int)fminf(fmaxf((qz - r - GMIN) * GINV, 0.f), (float)(NG - 1));
    int bz1 = (int)fminf(fmaxf((qz + r - GMIN) * GINV, 0.f), (float)(NG - 1));

    // phase 2: per-lane row scans over own box (divergence = masked lanes;
    // warp cost = max own-lane work). Overshoot <=1 pair per row: safe
    // (idempotent min; pads s=3e38 never win).
    for (int bz = bz0; bz <= bz1; ++bz) {
        for (int by = by0; by <= by1; ++by) {
            int iy  = (bz & 1) ? (NG - 1 - by) : by;
            int dir = (by + bz) & 1;
            int ic0 = dir ? (NG - 1 - bx1) : bx0;
            int ic1 = dir ? (NG - 1 - bx0) : bx1;
            int rowbase = (bz * NG + iy) * NG;
            int c0 = rowbase + ic0, c1 = rowbase + ic1;
            int is = c0 ? sends[c0 - 1] : 0;
            int ie = sends[c1];
            int jb = PADP + (is >> 1);
            int je = PADP + ((ie + 1) >> 1);
#pragma unroll 2
            for (int j = jb; j < je; ++j) PROCP(j);
        }
    }

    g_res[qset][qi] = fmaxf(fminf(bestA, bestB) + sqq, 0.f);
}

// ---- launches 5+6: reduction ------------------------------------------------
__global__ void reduce_partial_kernel()
{
    const int t = threadIdx.x, bid = blockIdx.x;
    const float* r = (const float*)g_res;
    float s = 0.f;
#pragma unroll
    for (int k = 0; k < 4; ++k)
        s += r[bid * 1024 + k * 256 + t];
#pragma unroll
    for (int o = 16; o > 0; o >>= 1)
        s += __shfl_down_sync(0xffffffffu, s, o);
    __shared__ float sh[8];
    if ((t & 31) == 0) sh[t >> 5] = s;
    __syncthreads();
    if (t == 0) {
        float v = 0.f;
#pragma unroll
        for (int w = 0; w < 8; ++w) v += sh[w];
        g_part[bid] = v;
    }
}

__global__ void final_kernel(float* __restrict__ out)
{
    const int t = threadIdx.x;   // 32
    double s = (double)g_part[t] + (double)g_part[t + 32];
#pragma unroll
    for (int o = 16; o > 0; o >>= 1)
        s += __shfl_down_sync(0xffffffffu, s, o);
    if (t == 0)
        out[0] = (float)sqrt(0.5 * s / (double)(NB * PTS));
}

extern "C" void kernel_launch(void* const* d_in, const int* in_sizes, int n_in,
                              void* d_out, int out_size)
{
    const float* yhat = (const float*)d_in[0];   // [B, N, 3]
    const float* y    = (const float*)d_in[1];   // [B, M, 3]
    (void)in_sizes; (void)n_in; (void)out_size;

    cudaFuncSetAttribute(search_kernel,
                         cudaFuncAttributeMaxDynamicSharedMemorySize,
                         SMEM_TOTAL);

    hist_kernel<<<128, 512>>>(yhat, y);              // 1
    scan1_kernel<<<256, 128>>>();                    // 2
    scatter_kernel<<<128, 512>>>(yhat, y);           // 3
    search_kernel<<<128, 512, SMEM_TOTAL>>>();       // 4 <- ncu capture slot
    reduce_partial_kernel<<<64, 256>>>();            // 5
    final_kernel<<<1, 32>>>((float*)d_out);          // 6
}